// round 4
// baseline (speedup 1.0000x reference)
#include <cuda_runtime.h>
#include <cuda_bf16.h>

// ---------------- problem constants ----------------
#define HDIM 128
#define CC 512                       // N_CENTROIDS
#define SENT (CC*CC)                 // 262144
#define NK (SENT+1)                  // key space 262145
#define NSLOT (CC*(CC-1)/2 + 1)      // E_COARSE+1 = 130817
#define EMAX 800000
#define NMAX 100000
#define BMAX 2

// ---------------- scratch (__device__ globals, no runtime alloc) ----------------
__device__ int   g_keys[EMAX];
__device__ int   g_order[EMAX];
__device__ int   g_cntk[NK];
__device__ int   g_eoff[NK];
__device__ int   g_cursor[NK];
__device__ int   g_slotkey[NSLOT];
__device__ int   g_rank_sent;                      // number of valid unique keys
__device__ __align__(16) float g_nodesum[BMAX*CC*HDIM];
__device__ int   g_ncnt[CC];
__device__ int   g_noff[CC];
__device__ int   g_ncursor[CC];
__device__ int   g_nodeperm[NMAX];

#define SCAN_BLK 1024
#define NSCAN ((NK + SCAN_BLK - 1) / SCAN_BLK)     // 257
__device__ int g_bsumC[NSCAN];
__device__ int g_bsumP[NSCAN];

// ---------------- zero scratch ----------------
__global__ void zero_scratch(int nodesum_elems) {
    int i = blockIdx.x * blockDim.x + threadIdx.x;
    if (i < NK)            { g_cntk[i] = 0; g_cursor[i] = 0; }
    if (i < nodesum_elems) g_nodesum[i] = 0.f;
    if (i < CC)            { g_ncnt[i] = 0; g_ncursor[i] = 0; }
}

// ---------------- edge pass 1: keys + per-key counts ----------------
__global__ void edge_key_kernel(const int* __restrict__ ei,
                                const int* __restrict__ cci, int E) {
    int e = blockIdx.x * blockDim.x + threadIdx.x;
    if (e >= E) return;
    int a = cci[ei[e]];
    int b = cci[ei[E + e]];
    int key;
    if (a == b) key = SENT;
    else {
        int lo = min(a, b), hi = max(a, b);
        key = lo * CC + hi;
    }
    g_keys[e] = key;
    atomicAdd(&g_cntk[key], 1);
}

// ---------------- node counts + tail outputs (cci, distances) ----------------
__global__ void node_misc_kernel(const int* __restrict__ cci,
                                 const float* __restrict__ dist,
                                 float* __restrict__ out,
                                 int N, size_t off3, size_t off4) {
    int n = blockIdx.x * blockDim.x + threadIdx.x;
    if (n >= N) return;
    int c = cci[n];
    atomicAdd(&g_ncnt[c], 1);
    out[off3 + n] = (float)c;
    out[off4 + n] = dist[n];
}

// ---------------- node CSR: exclusive scan over 512 centroid counts ----------------
__global__ void node_scan_kernel() {
    int t = threadIdx.x;                    // 512 threads, 1 block
    __shared__ int s[CC];
    int v = g_ncnt[t];
    s[t] = v; __syncthreads();
    for (int st = 1; st < CC; st <<= 1) {
        int a = (t >= st) ? s[t - st] : 0;
        __syncthreads();
        s[t] += a;
        __syncthreads();
    }
    g_noff[t] = s[t] - v;                   // exclusive
}

// ---------------- node scatter: perm of node ids sorted by centroid ----------------
__global__ void node_scatter_kernel(const int* __restrict__ cci, int N) {
    int n = blockIdx.x * blockDim.x + threadIdx.x;
    if (n >= N) return;
    int c = cci[n];
    int p = atomicAdd(&g_ncursor[c], 1);
    g_nodeperm[g_noff[c] + p] = n;
}

// ---------------- scan pass 1: per-block sums (counts, presence) ----------------
__global__ void scan_pass1() {
    int t  = threadIdx.x;
    int b0 = blockIdx.x * SCAN_BLK + t * 4;
    int c = 0, p = 0;
#pragma unroll
    for (int i = 0; i < 4; i++) {
        int k = b0 + i;
        if (k < NK) { int v = g_cntk[k]; c += v; p += (v > 0); }
    }
    __shared__ int sC[256], sP[256];
    sC[t] = c; sP[t] = p; __syncthreads();
    for (int s = 128; s > 0; s >>= 1) {
        if (t < s) { sC[t] += sC[t + s]; sP[t] += sP[t + s]; }
        __syncthreads();
    }
    if (t == 0) { g_bsumC[blockIdx.x] = sC[0]; g_bsumP[blockIdx.x] = sP[0]; }
}

// ---------------- scan pass 2: full exclusive scan, slotkey, uvalid ----------------
__global__ void scan_pass2() {
    int t = threadIdx.x;
    __shared__ int sC[256], sP[256];
    int vc = (t < blockIdx.x) ? g_bsumC[t] : 0;   // blockIdx.x <= 256
    int vp = (t < blockIdx.x) ? g_bsumP[t] : 0;
    sC[t] = vc; sP[t] = vp; __syncthreads();
    for (int s = 128; s > 0; s >>= 1) {
        if (t < s) { sC[t] += sC[t + s]; sP[t] += sP[t + s]; }
        __syncthreads();
    }
    int baseC = sC[0], baseP = sP[0];
    __syncthreads();

    int b0 = blockIdx.x * SCAN_BLK + t * 4;
    int cv[4]; int c = 0, p = 0;
#pragma unroll
    for (int i = 0; i < 4; i++) {
        int k = b0 + i;
        cv[i] = (k < NK) ? g_cntk[k] : 0;
        c += cv[i]; p += (cv[i] > 0);
    }
    sC[t] = c; sP[t] = p; __syncthreads();
    for (int s = 1; s < 256; s <<= 1) {
        int ac = (t >= s) ? sC[t - s] : 0;
        int ap = (t >= s) ? sP[t - s] : 0;
        __syncthreads();
        sC[t] += ac; sP[t] += ap;
        __syncthreads();
    }
    int exC = baseC + sC[t] - c;
    int exP = baseP + sP[t] - p;
#pragma unroll
    for (int i = 0; i < 4; i++) {
        int k = b0 + i;
        if (k < NK) {
            g_eoff[k] = exC;
            if (cv[i] > 0 && k < SENT) g_slotkey[exP] = k;
            if (k == SENT) g_rank_sent = exP;
            exC += cv[i];
            exP += (cv[i] > 0);
        }
    }
}

// ---------------- edge pass 2: CSR scatter ----------------
__global__ void scatter_kernel(int E) {
    int e = blockIdx.x * blockDim.x + threadIdx.x;
    if (e >= E) return;
    int k = g_keys[e];
    int p = atomicAdd(&g_cursor[k], 1);
    g_order[g_eoff[k] + p] = e;
}

// -------- fused MLP (SGEMM+ReLU, f32x2 FMA) + sorted-run pooled RED.v4 --------
#define TILE_R 128
#define KC 32
__global__ __launch_bounds__(256, 2)
void mlp_pool_kernel(const float* __restrict__ x,
                     const float* __restrict__ dists,
                     const int*   __restrict__ cci,
                     const float* __restrict__ W,
                     const float* __restrict__ bias,
                     int N, int R) {
    __shared__ float As[TILE_R][KC + 4];
    __shared__ float Ws[KC][HDIM];
    __shared__ int   sSrc[TILE_R];      // permuted global row (b*N + n), -1 if OOB
    __shared__ int   sKey[TILE_R];      // b*CC + centroid
    __shared__ float sDr[TILE_R];       // distance
    int tid = threadIdx.x;
    int tx = tid & 15, ty = tid >> 4;
    int rowBase = blockIdx.x * TILE_R;

    if (tid < TILE_R) {
        int rr = rowBase + tid;
        if (rr < R) {
            int bb  = rr / N;
            int pos = rr - bb * N;
            int n   = g_nodeperm[pos];
            sSrc[tid] = bb * N + n;
            sKey[tid] = bb * CC + cci[n];
            sDr[tid]  = dists[n];
        } else { sSrc[tid] = -1; sKey[tid] = -1; sDr[tid] = 0.f; }
    }
    __syncthreads();

    unsigned long long accP[8][4];     // 8 rows x 4 f32x2 col-pairs
#pragma unroll
    for (int i = 0; i < 8; i++)
#pragma unroll
        for (int j = 0; j < 4; j++) accP[i][j] = 0ull;

    for (int kt = 0; kt < HDIM; kt += KC) {
#pragma unroll
        for (int i = 0; i < (TILE_R * KC) / 256; i++) {
            int idx = tid + i * 256;
            int r = idx >> 5, cidx = idx & 31;
            int gr = sSrc[r];
            As[r][cidx] = (gr >= 0) ? x[(size_t)gr * HDIM + kt + cidx] : 0.f;
        }
#pragma unroll
        for (int i = 0; i < (KC * HDIM) / 256; i++) {
            int idx = tid + i * 256;
            int k = idx >> 7, h = idx & 127;
            Ws[k][h] = W[(size_t)(kt + k) * HDIM + h];
        }
        __syncthreads();
#pragma unroll
        for (int k = 0; k < KC; k++) {
            float a[8];
            unsigned long long wp[4];
#pragma unroll
            for (int i = 0; i < 8; i++) a[i] = As[ty * 8 + i][k];
            const float2* wrow = reinterpret_cast<const float2*>(&Ws[k][tx * 8]);
#pragma unroll
            for (int j = 0; j < 4; j++) {
                float2 w2 = wrow[j];
                asm("mov.b64 %0, {%1, %2};" : "=l"(wp[j]) : "f"(w2.x), "f"(w2.y));
            }
#pragma unroll
            for (int i = 0; i < 8; i++) {
                unsigned long long ap;
                asm("mov.b64 %0, {%1, %1};" : "=l"(ap) : "f"(a[i]));
#pragma unroll
                for (int j = 0; j < 4; j++)
                    asm("fma.rn.f32x2 %0, %1, %2, %0;"
                        : "+l"(accP[i][j]) : "l"(ap), "l"(wp[j]));
            }
        }
        __syncthreads();
    }

    // epilogue: bias + distance term + ReLU, run-length aggregate by key, RED.v4
    const float* Wlast = W + (size_t)HDIM * HDIM;   // distance row (row H)
    float bcol[8], wlcol[8];
#pragma unroll
    for (int j = 0; j < 8; j++) {
        bcol[j]  = bias[tx * 8 + j];
        wlcol[j] = Wlast[tx * 8 + j];
    }
    float run[8];
#pragma unroll
    for (int j = 0; j < 8; j++) run[j] = 0.f;
    int runKey = -1;
#pragma unroll
    for (int i = 0; i < 8; i++) {
        int rl  = ty * 8 + i;
        int key = sKey[rl];
        if (key < 0) continue;
        if (key != runKey) {
            if (runKey >= 0) {
                float* dst = g_nodesum + (size_t)runKey * HDIM + tx * 8;
                asm volatile("red.global.add.v4.f32 [%0], {%1, %2, %3, %4};"
                             :: "l"(dst), "f"(run[0]), "f"(run[1]), "f"(run[2]), "f"(run[3])
                             : "memory");
                asm volatile("red.global.add.v4.f32 [%0], {%1, %2, %3, %4};"
                             :: "l"(dst + 4), "f"(run[4]), "f"(run[5]), "f"(run[6]), "f"(run[7])
                             : "memory");
            }
            runKey = key;
#pragma unroll
            for (int j = 0; j < 8; j++) run[j] = 0.f;
        }
        float dr = sDr[rl];
#pragma unroll
        for (int j = 0; j < 4; j++) {
            float vlo, vhi;
            asm("mov.b64 {%0, %1}, %2;" : "=f"(vlo), "=f"(vhi) : "l"(accP[i][j]));
            run[2*j]   += fmaxf(vlo + dr * wlcol[2*j]   + bcol[2*j],   0.f);
            run[2*j+1] += fmaxf(vhi + dr * wlcol[2*j+1] + bcol[2*j+1], 0.f);
        }
    }
    if (runKey >= 0) {
        float* dst = g_nodesum + (size_t)runKey * HDIM + tx * 8;
        asm volatile("red.global.add.v4.f32 [%0], {%1, %2, %3, %4};"
                     :: "l"(dst), "f"(run[0]), "f"(run[1]), "f"(run[2]), "f"(run[3])
                     : "memory");
        asm volatile("red.global.add.v4.f32 [%0], {%1, %2, %3, %4};"
                     :: "l"(dst + 4), "f"(run[4]), "f"(run[5]), "f"(run[6]), "f"(run[7])
                     : "memory");
    }
}

// ---------------- node_avg writeout ----------------
__global__ void node_avg_kernel(float* __restrict__ out, int total) {
    int i = blockIdx.x * blockDim.x + threadIdx.x;
    if (i >= total) return;
    int c = (i >> 7) & (CC - 1);     // (i/H) % CC  with H=128, CC=512
    out[i] = g_nodesum[i] / fmaxf((float)g_ncnt[c], 1.f);
}

// ---- coarse-edge gather-mean (edge-major loop: load index once, both batches) ----
__global__ void coarse_edge_kernel(const float* __restrict__ ea,
                                   float* __restrict__ out,
                                   int E, int B, size_t off1, size_t off2) {
    int w    = (blockIdx.x * blockDim.x + threadIdx.x) >> 5;
    int lane = threadIdx.x & 31;
    if (w >= NSLOT) return;
    int uvalid = g_rank_sent;
    float* cea = out + off1;
    float* ce  = out + off2;
    if (w < uvalid) {
        int k   = g_slotkey[w];
        int cnt = g_cntk[k];
        int off = g_eoff[k];
        float inv = 1.0f / (float)cnt;
        float4 acc[BMAX];
#pragma unroll
        for (int bb = 0; bb < BMAX; bb++) acc[bb] = make_float4(0.f, 0.f, 0.f, 0.f);
        for (int i = 0; i < cnt; i++) {
            int e = g_order[off + i];
            const float* rowp = ea + (size_t)e * HDIM + lane * 4;
#pragma unroll
            for (int bb = 0; bb < BMAX; bb++) {
                if (bb >= B) break;
                float4 v = *reinterpret_cast<const float4*>(rowp + (size_t)bb * E * HDIM);
                acc[bb].x += v.x; acc[bb].y += v.y; acc[bb].z += v.z; acc[bb].w += v.w;
            }
        }
#pragma unroll
        for (int bb = 0; bb < BMAX; bb++) {
            if (bb >= B) break;
            float4 r = acc[bb];
            r.x *= inv; r.y *= inv; r.z *= inv; r.w *= inv;
            *reinterpret_cast<float4*>(cea + ((size_t)bb * NSLOT + w) * HDIM + lane * 4) = r;
        }
        if (lane == 0) {
            ce[w]         = (float)(k >> 9);      // k / 512
            ce[NSLOT + w] = (float)(k & 511);     // k % 512
        }
    } else {
        float4 z = make_float4(0.f, 0.f, 0.f, 0.f);
        for (int bb = 0; bb < B; bb++)
            *reinterpret_cast<float4*>(cea + ((size_t)bb * NSLOT + w) * HDIM + lane * 4) = z;
        if (lane == 0) { ce[w] = -1.f; ce[NSLOT + w] = -1.f; }
    }
}

// ---------------- launcher ----------------
extern "C" void kernel_launch(void* const* d_in, const int* in_sizes, int n_in,
                              void* d_out, int out_size) {
    const float* x    = (const float*)d_in[0];
    const int*   ei   = (const int*)  d_in[1];
    const float* ea   = (const float*)d_in[2];
    // d_in[3] = scale (unused)
    const int*   cci  = (const int*)  d_in[4];
    const float* dist = (const float*)d_in[5];
    const float* W    = (const float*)d_in[6];
    const float* bias = (const float*)d_in[7];
    float* out = (float*)d_out;

    int N = in_sizes[4];
    int E = in_sizes[1] / 2;
    int B = (int)((long long)in_sizes[0] / ((long long)N * HDIM));
    int R = B * N;

    size_t off1 = (size_t)B * CC * HDIM;                 // coarse_edge_attrs
    size_t off2 = off1 + (size_t)B * NSLOT * HDIM;       // coarse_edges
    size_t off3 = off2 + 2 * (size_t)NSLOT;              // cci
    size_t off4 = off3 + (size_t)N;                      // distances

    int nodesum_elems = B * CC * HDIM;

    zero_scratch<<<(NK + 255) / 256, 256>>>(nodesum_elems);
    edge_key_kernel<<<(E + 255) / 256, 256>>>(ei, cci, E);
    node_misc_kernel<<<(N + 255) / 256, 256>>>(cci, dist, out, N, off3, off4);
    node_scan_kernel<<<1, CC>>>();
    node_scatter_kernel<<<(N + 255) / 256, 256>>>(cci, N);
    scan_pass1<<<NSCAN, 256>>>();
    scan_pass2<<<NSCAN, 256>>>();
    scatter_kernel<<<(E + 255) / 256, 256>>>(E);
    mlp_pool_kernel<<<(R + TILE_R - 1) / TILE_R, 256>>>(x, dist, cci, W, bias, N, R);
    node_avg_kernel<<<(nodesum_elems + 255) / 256, 256>>>(out, nodesum_elems);
    {
        long long threads = (long long)NSLOT * 32;
        int blocks = (int)((threads + 255) / 256);
        coarse_edge_kernel<<<blocks, 256>>>(ea, out, E, B, off1, off2);
    }
}

// round 5
// speedup vs baseline: 1.0154x; 1.0154x over previous
#include <cuda_runtime.h>
#include <cuda_bf16.h>

// ---------------- problem constants ----------------
#define HDIM 128
#define CC 512                       // N_CENTROIDS
#define SENT (CC*CC)                 // 262144
#define NK (SENT+1)                  // key space 262145
#define NSLOT (CC*(CC-1)/2 + 1)      // E_COARSE+1 = 130817
#define EMAX 800000
#define NMAX 100000
#define BMAX 2

// ---------------- scratch (__device__ globals, no runtime alloc) ----------------
__device__ int   g_keys[EMAX];
__device__ int   g_order[EMAX];
__device__ int   g_cntk[NK];
__device__ int   g_eoff[NK];
__device__ int   g_cursor[NK];
__device__ int   g_slotkey[NSLOT];
__device__ int   g_rank_sent;
__device__ __align__(16) float g_nodesum[BMAX*CC*HDIM];
__device__ int   g_ncnt[CC];
__device__ int   g_noff[CC];
__device__ int   g_ncursor[CC];
__device__ int   g_nodeperm[NMAX];

#define SCAN_BLK 1024
#define NSCAN ((NK + SCAN_BLK - 1) / SCAN_BLK)     // 257
__device__ int g_bsumC[NSCAN];
__device__ int g_bsumP[NSCAN];

// ---------------- zero scratch ----------------
__global__ void zero_scratch(int nodesum_elems) {
    int i = blockIdx.x * blockDim.x + threadIdx.x;
    if (i < NK)            { g_cntk[i] = 0; g_cursor[i] = 0; }
    if (i < nodesum_elems) g_nodesum[i] = 0.f;
    if (i < CC)            { g_ncnt[i] = 0; g_ncursor[i] = 0; }
}

// ---------------- edge pass 1: keys + per-key counts ----------------
__global__ void edge_key_kernel(const int* __restrict__ ei,
                                const int* __restrict__ cci, int E) {
    int e = blockIdx.x * blockDim.x + threadIdx.x;
    if (e >= E) return;
    int a = cci[ei[e]];
    int b = cci[ei[E + e]];
    int key;
    if (a == b) key = SENT;
    else {
        int lo = min(a, b), hi = max(a, b);
        key = lo * CC + hi;
    }
    g_keys[e] = key;
    atomicAdd(&g_cntk[key], 1);
}

// ---------------- node counts + tail outputs (cci, distances) ----------------
__global__ void node_misc_kernel(const int* __restrict__ cci,
                                 const float* __restrict__ dist,
                                 float* __restrict__ out,
                                 int N, size_t off3, size_t off4) {
    int n = blockIdx.x * blockDim.x + threadIdx.x;
    if (n >= N) return;
    int c = cci[n];
    atomicAdd(&g_ncnt[c], 1);
    out[off3 + n] = (float)c;
    out[off4 + n] = dist[n];
}

// ---------------- node CSR: exclusive scan over 512 centroid counts ----------------
__global__ void node_scan_kernel() {
    int t = threadIdx.x;                    // 512 threads, 1 block
    __shared__ int s[CC];
    int v = g_ncnt[t];
    s[t] = v; __syncthreads();
    for (int st = 1; st < CC; st <<= 1) {
        int a = (t >= st) ? s[t - st] : 0;
        __syncthreads();
        s[t] += a;
        __syncthreads();
    }
    g_noff[t] = s[t] - v;                   // exclusive
}

// ---------------- node scatter: perm of node ids sorted by centroid ----------------
__global__ void node_scatter_kernel(const int* __restrict__ cci, int N) {
    int n = blockIdx.x * blockDim.x + threadIdx.x;
    if (n >= N) return;
    int c = cci[n];
    int p = atomicAdd(&g_ncursor[c], 1);
    g_nodeperm[g_noff[c] + p] = n;
}

// ---------------- scan pass 1: per-block sums (counts, presence) ----------------
__global__ void scan_pass1() {
    int t  = threadIdx.x;
    int b0 = blockIdx.x * SCAN_BLK + t * 4;
    int c = 0, p = 0;
#pragma unroll
    for (int i = 0; i < 4; i++) {
        int k = b0 + i;
        if (k < NK) { int v = g_cntk[k]; c += v; p += (v > 0); }
    }
    __shared__ int sC[256], sP[256];
    sC[t] = c; sP[t] = p; __syncthreads();
    for (int s = 128; s > 0; s >>= 1) {
        if (t < s) { sC[t] += sC[t + s]; sP[t] += sP[t + s]; }
        __syncthreads();
    }
    if (t == 0) { g_bsumC[blockIdx.x] = sC[0]; g_bsumP[blockIdx.x] = sP[0]; }
}

// ---------------- scan pass 2: full exclusive scan, slotkey, uvalid ----------------
__global__ void scan_pass2() {
    int t = threadIdx.x;
    __shared__ int sC[256], sP[256];
    int vc = (t < blockIdx.x) ? g_bsumC[t] : 0;   // blockIdx.x <= 256
    int vp = (t < blockIdx.x) ? g_bsumP[t] : 0;
    sC[t] = vc; sP[t] = vp; __syncthreads();
    for (int s = 128; s > 0; s >>= 1) {
        if (t < s) { sC[t] += sC[t + s]; sP[t] += sP[t + s]; }
        __syncthreads();
    }
    int baseC = sC[0], baseP = sP[0];
    __syncthreads();

    int b0 = blockIdx.x * SCAN_BLK + t * 4;
    int cv[4]; int c = 0, p = 0;
#pragma unroll
    for (int i = 0; i < 4; i++) {
        int k = b0 + i;
        cv[i] = (k < NK) ? g_cntk[k] : 0;
        c += cv[i]; p += (cv[i] > 0);
    }
    sC[t] = c; sP[t] = p; __syncthreads();
    for (int s = 1; s < 256; s <<= 1) {
        int ac = (t >= s) ? sC[t - s] : 0;
        int ap = (t >= s) ? sP[t - s] : 0;
        __syncthreads();
        sC[t] += ac; sP[t] += ap;
        __syncthreads();
    }
    int exC = baseC + sC[t] - c;
    int exP = baseP + sP[t] - p;
#pragma unroll
    for (int i = 0; i < 4; i++) {
        int k = b0 + i;
        if (k < NK) {
            g_eoff[k] = exC;
            if (cv[i] > 0 && k < SENT) g_slotkey[exP] = k;
            if (k == SENT) g_rank_sent = exP;
            exC += cv[i];
            exP += (cv[i] > 0);
        }
    }
}

// ---------------- edge pass 2: CSR scatter ----------------
__global__ void scatter_kernel(int E) {
    int e = blockIdx.x * blockDim.x + threadIdx.x;
    if (e >= E) return;
    int k = g_keys[e];
    int p = atomicAdd(&g_cursor[k], 1);
    g_order[g_eoff[k] + p] = e;
}

// ---- coarse-edge gather-mean (streaming loads, edge-major loop) ----
__global__ void coarse_edge_kernel(const float* __restrict__ ea,
                                   float* __restrict__ out,
                                   int E, int B, size_t off1, size_t off2) {
    int w    = (blockIdx.x * blockDim.x + threadIdx.x) >> 5;
    int lane = threadIdx.x & 31;
    if (w >= NSLOT) return;
    int uvalid = g_rank_sent;
    float* cea = out + off1;
    float* ce  = out + off2;
    if (w < uvalid) {
        int k   = g_slotkey[w];
        int cnt = g_cntk[k];
        int off = g_eoff[k];
        float inv = 1.0f / (float)cnt;
        float4 acc[BMAX];
#pragma unroll
        for (int bb = 0; bb < BMAX; bb++) acc[bb] = make_float4(0.f, 0.f, 0.f, 0.f);
        for (int i = 0; i < cnt; i++) {
            int e = g_order[off + i];
            const float4* rowp = reinterpret_cast<const float4*>(ea + (size_t)e * HDIM) + lane;
#pragma unroll
            for (int bb = 0; bb < BMAX; bb++) {
                if (bb >= B) break;
                float4 v = __ldcs(rowp + (size_t)bb * (E * (HDIM / 4)));
                acc[bb].x += v.x; acc[bb].y += v.y; acc[bb].z += v.z; acc[bb].w += v.w;
            }
        }
#pragma unroll
        for (int bb = 0; bb < BMAX; bb++) {
            if (bb >= B) break;
            float4 r = acc[bb];
            r.x *= inv; r.y *= inv; r.z *= inv; r.w *= inv;
            *reinterpret_cast<float4*>(cea + ((size_t)bb * NSLOT + w) * HDIM + lane * 4) = r;
        }
        if (lane == 0) {
            ce[w]         = (float)(k >> 9);      // k / 512
            ce[NSLOT + w] = (float)(k & 511);     // k % 512
        }
    } else {
        float4 z = make_float4(0.f, 0.f, 0.f, 0.f);
        for (int bb = 0; bb < B; bb++)
            *reinterpret_cast<float4*>(cea + ((size_t)bb * NSLOT + w) * HDIM + lane * 4) = z;
        if (lane == 0) { ce[w] = -1.f; ce[NSLOT + w] = -1.f; }
    }
}

// -------- fused MLP (SGEMM+ReLU, f32x2 FMA, conflict-free column swizzle) --------
// per-thread columns: pairs at 2*tx + 32*j  (j = 0..3)  -> w-LDS are 128B/phase
#define TILE_R 128
#define KC 32
__global__ __launch_bounds__(256, 2)
void mlp_pool_kernel(const float* __restrict__ x,
                     const float* __restrict__ dists,
                     const int*   __restrict__ cci,
                     const float* __restrict__ W,
                     const float* __restrict__ bias,
                     int N, int R) {
    __shared__ float As[TILE_R][KC + 4];
    __shared__ float Ws[KC][HDIM];
    __shared__ int   sSrc[TILE_R];
    __shared__ int   sKey[TILE_R];
    __shared__ float sDr[TILE_R];
    int tid = threadIdx.x;
    int tx = tid & 15, ty = tid >> 4;
    int rowBase = blockIdx.x * TILE_R;

    if (tid < TILE_R) {
        int rr = rowBase + tid;
        if (rr < R) {
            int bb  = rr / N;
            int pos = rr - bb * N;
            int n   = g_nodeperm[pos];
            sSrc[tid] = bb * N + n;
            sKey[tid] = bb * CC + cci[n];
            sDr[tid]  = dists[n];
        } else { sSrc[tid] = -1; sKey[tid] = -1; sDr[tid] = 0.f; }
    }
    __syncthreads();

    unsigned long long accP[8][4];     // 8 rows x 4 f32x2 col-pairs (cols 2tx+32j, +1)
#pragma unroll
    for (int i = 0; i < 8; i++)
#pragma unroll
        for (int j = 0; j < 4; j++) accP[i][j] = 0ull;

    for (int kt = 0; kt < HDIM; kt += KC) {
#pragma unroll
        for (int i = 0; i < (TILE_R * KC) / 256; i++) {
            int idx = tid + i * 256;
            int r = idx >> 5, cidx = idx & 31;
            int gr = sSrc[r];
            As[r][cidx] = (gr >= 0) ? x[(size_t)gr * HDIM + kt + cidx] : 0.f;
        }
#pragma unroll
        for (int i = 0; i < (KC * HDIM) / 256; i++) {
            int idx = tid + i * 256;
            int k = idx >> 7, h = idx & 127;
            Ws[k][h] = W[(size_t)(kt + k) * HDIM + h];
        }
        __syncthreads();
#pragma unroll
        for (int k = 0; k < KC; k++) {
            float a[8];
            unsigned long long wp[4];
#pragma unroll
            for (int i = 0; i < 8; i++) a[i] = As[ty * 8 + i][k];
#pragma unroll
            for (int j = 0; j < 4; j++) {
                float2 w2 = *reinterpret_cast<const float2*>(&Ws[k][2 * tx + 32 * j]);
                asm("mov.b64 %0, {%1, %2};" : "=l"(wp[j]) : "f"(w2.x), "f"(w2.y));
            }
#pragma unroll
            for (int i = 0; i < 8; i++) {
                unsigned long long ap;
                asm("mov.b64 %0, {%1, %1};" : "=l"(ap) : "f"(a[i]));
#pragma unroll
                for (int j = 0; j < 4; j++)
                    asm("fma.rn.f32x2 %0, %1, %2, %0;"
                        : "+l"(accP[i][j]) : "l"(ap), "l"(wp[j]));
            }
        }
        __syncthreads();
    }

    // epilogue: bias + distance + ReLU, run-length aggregate by key, RED.v2 x4
    const float* Wlast = W + (size_t)HDIM * HDIM;
    float bcol[8], wlcol[8];
#pragma unroll
    for (int j = 0; j < 4; j++) {
        int col = 2 * tx + 32 * j;
        bcol[2*j]   = bias[col];     bcol[2*j+1]  = bias[col + 1];
        wlcol[2*j]  = Wlast[col];    wlcol[2*j+1] = Wlast[col + 1];
    }
    float run[8];
#pragma unroll
    for (int j = 0; j < 8; j++) run[j] = 0.f;
    int runKey = -1;
#pragma unroll
    for (int i = 0; i < 8; i++) {
        int rl  = ty * 8 + i;
        int key = sKey[rl];
        if (key < 0) continue;
        if (key != runKey) {
            if (runKey >= 0) {
                float* base = g_nodesum + (size_t)runKey * HDIM + 2 * tx;
#pragma unroll
                for (int j = 0; j < 4; j++)
                    asm volatile("red.global.add.v2.f32 [%0], {%1, %2};"
                                 :: "l"(base + 32 * j), "f"(run[2*j]), "f"(run[2*j+1])
                                 : "memory");
            }
            runKey = key;
#pragma unroll
            for (int j = 0; j < 8; j++) run[j] = 0.f;
        }
        float dr = sDr[rl];
#pragma unroll
        for (int j = 0; j < 4; j++) {
            float vlo, vhi;
            asm("mov.b64 {%0, %1}, %2;" : "=f"(vlo), "=f"(vhi) : "l"(accP[i][j]));
            run[2*j]   += fmaxf(vlo + dr * wlcol[2*j]   + bcol[2*j],   0.f);
            run[2*j+1] += fmaxf(vhi + dr * wlcol[2*j+1] + bcol[2*j+1], 0.f);
        }
    }
    if (runKey >= 0) {
        float* base = g_nodesum + (size_t)runKey * HDIM + 2 * tx;
#pragma unroll
        for (int j = 0; j < 4; j++)
            asm volatile("red.global.add.v2.f32 [%0], {%1, %2};"
                         :: "l"(base + 32 * j), "f"(run[2*j]), "f"(run[2*j+1])
                         : "memory");
    }
}

// ---------------- node_avg writeout ----------------
__global__ void node_avg_kernel(float* __restrict__ out, int total) {
    int i = blockIdx.x * blockDim.x + threadIdx.x;
    if (i >= total) return;
    int c = (i >> 7) & (CC - 1);
    out[i] = g_nodesum[i] / fmaxf((float)g_ncnt[c], 1.f);
}

// ---------------- launcher (coarse_edge is launch index 5 for ncu -s 5) ----------
extern "C" void kernel_launch(void* const* d_in, const int* in_sizes, int n_in,
                              void* d_out, int out_size) {
    const float* x    = (const float*)d_in[0];
    const int*   ei   = (const int*)  d_in[1];
    const float* ea   = (const float*)d_in[2];
    // d_in[3] = scale (unused)
    const int*   cci  = (const int*)  d_in[4];
    const float* dist = (const float*)d_in[5];
    const float* W    = (const float*)d_in[6];
    const float* bias = (const float*)d_in[7];
    float* out = (float*)d_out;

    int N = in_sizes[4];
    int E = in_sizes[1] / 2;
    int B = (int)((long long)in_sizes[0] / ((long long)N * HDIM));
    int R = B * N;

    size_t off1 = (size_t)B * CC * HDIM;                 // coarse_edge_attrs
    size_t off2 = off1 + (size_t)B * NSLOT * HDIM;       // coarse_edges
    size_t off3 = off2 + 2 * (size_t)NSLOT;              // cci
    size_t off4 = off3 + (size_t)N;                      // distances

    int nodesum_elems = B * CC * HDIM;

    zero_scratch<<<(NK + 255) / 256, 256>>>(nodesum_elems);            // 0
    edge_key_kernel<<<(E + 255) / 256, 256>>>(ei, cci, E);             // 1
    scan_pass1<<<NSCAN, 256>>>();                                      // 2
    scan_pass2<<<NSCAN, 256>>>();                                      // 3
    scatter_kernel<<<(E + 255) / 256, 256>>>(E);                       // 4
    {
        long long threads = (long long)NSLOT * 32;
        int blocks = (int)((threads + 255) / 256);
        coarse_edge_kernel<<<blocks, 256>>>(ea, out, E, B, off1, off2); // 5 (profiled)
    }
    node_misc_kernel<<<(N + 255) / 256, 256>>>(cci, dist, out, N, off3, off4); // 6
    node_scan_kernel<<<1, CC>>>();                                     // 7
    node_scatter_kernel<<<(N + 255) / 256, 256>>>(cci, N);             // 8
    mlp_pool_kernel<<<(R + TILE_R - 1) / TILE_R, 256>>>(x, dist, cci, W, bias, N, R); // 9
    node_avg_kernel<<<(nodesum_elems + 255) / 256, 256>>>(out, nodesum_elems);        // 10
}